// round 1
// baseline (speedup 1.0000x reference)
#include <cuda_runtime.h>
#include <cuda_bf16.h>
#include <math.h>

// Problem constants
#define BB 4
#define CIN 3
#define CC 32
#define HH 256
#define WW 256
#define MM 16
#define NB 4
#define OC 4
#define PIX (HH*WW)

// Scratch (device globals: allocation-free)
__device__ float  g_x0[BB*CC*PIX];
__device__ float  g_xa[BB*CC*PIX];
__device__ float  g_xb[BB*CC*PIX];
__device__ float2 g_S [BB*CC*HH*MM];
__device__ float2 g_X [BB*CC*MM*MM];
__device__ float2 g_Y [BB*CC*MM*MM];
__device__ float2 g_Bf[BB*CC*HH*MM];
__device__ float2 g_W [OC*NB*MM*MM*CC*CC];   // [ohn][k*16+l][c][o]
__device__ float  g_ct[256];
__device__ float  g_st[256];

__global__ void init_tw() {
    int t = threadIdx.x;
    double a = 6.283185307179586476925286766559 * (double)t / 256.0;
    g_ct[t] = (float)cos(a);
    g_st[t] = (float)sin(a);
}

// Transpose weights: src [ohn][i][o][k][l]  ->  dst [ohn][k*16+l][i][o] as float2(re,im)
__global__ void init_w(const float* __restrict__ wr, const float* __restrict__ wi) {
    long d = (long)blockIdx.x * blockDim.x + threadIdx.x;   // 4*4*16*16*32*32 = 4194304
    int o   = (int)(d & 31);
    int c   = (int)((d >> 5) & 31);
    int kl  = (int)((d >> 10) & 255);
    int ohn = (int)(d >> 18);
    int k = kl >> 4, l = kl & 15;
    long s = ((((long)ohn * 32 + c) * 32 + o) * 16 + k) * 16 + l;
    g_W[d] = make_float2(wr[s], wi[s]);
}

// Lift: x[B,3,H,W] -> g_x0[B,32,H,W]
__global__ void klift(const float* __restrict__ x, const float* __restrict__ lw,
                      const float* __restrict__ lb) {
    int idx = blockIdx.x * 256 + threadIdx.x;   // 8388608 total
    int pix = idx & (PIX - 1);
    int bc  = idx >> 16;
    int c = bc & 31, b = bc >> 5;
    float acc = lb[c];
    #pragma unroll
    for (int i = 0; i < CIN; i++)
        acc = fmaf(x[(b * CIN + i) * PIX + pix], lw[c * CIN + i], acc);
    g_x0[idx] = acc;
}

// K1: W-axis truncated DFT. S[b,c,h,m] = sum_w x[b,c,h,w] * e^{-2pi i m w/256}
__global__ void k1(const float* __restrict__ xin) {
    __shared__ float xs[16 * 256];
    int row0 = blockIdx.x * 16;                 // global row = (b*32+c)*256 + h
    for (int i = threadIdx.x; i < 16 * 256; i += 256)
        xs[i] = xin[(long)row0 * 256 + i];
    __syncthreads();
    int r = threadIdx.x >> 4, m = threadIdx.x & 15;
    float cstep = g_ct[m], sstep = -g_st[m];    // e^{-2pi i m/256}
    float c = 1.f, s = 0.f, ar = 0.f, ai = 0.f;
    const float* xr = xs + r * 256;
    #pragma unroll 8
    for (int w = 0; w < 256; w++) {
        float v = xr[w];
        ar = fmaf(v, c, ar);
        ai = fmaf(v, s, ai);
        float c2 = c * cstep - s * sstep;
        s = fmaf(c, sstep, s * cstep);
        c = c2;
    }
    g_S[(long)(row0 + r) * 16 + m] = make_float2(ar, ai);
}

// K2a: H-axis truncated DFT + ortho 1/256. X[b,c,k,l] = (1/256) sum_h S[h,l] e^{-2pi i k h/256}
__global__ void k2a() {
    __shared__ float2 Ss[256 * 16];
    int bc = blockIdx.x;                        // 128
    const float2* src = g_S + (long)bc * 256 * 16;
    for (int i = threadIdx.x; i < 4096; i += 256) Ss[i] = src[i];
    __syncthreads();
    int k = threadIdx.x >> 4, l = threadIdx.x & 15;
    float cstep = g_ct[k], sstep = -g_st[k];
    float c = 1.f, s = 0.f, ar = 0.f, ai = 0.f;
    #pragma unroll 8
    for (int h = 0; h < 256; h++) {
        float2 v = Ss[h * 16 + l];
        ar += v.x * c - v.y * s;
        ai += v.x * s + v.y * c;
        float c2 = c * cstep - s * sstep;
        s = fmaf(c, sstep, s * cstep);
        c = c2;
    }
    g_X[bc * 256 + threadIdx.x] = make_float2(ar * (1.f / 256.f), ai * (1.f / 256.f));
}

// K2b: channel mix per (k,l): Y[b,o] = sum_c X[b,c] * W[c,o]
__global__ void k2b(const float2* __restrict__ Wt) {
    __shared__ float2 Ws[32 * 32];              // [c][o]
    __shared__ float2 Xs[4][32];
    int kl = blockIdx.x;                        // 256
    for (int i = threadIdx.x; i < 1024; i += 128) Ws[i] = Wt[(long)kl * 1024 + i];
    {
        int b = threadIdx.x >> 5, c = threadIdx.x & 31;
        Xs[b][c] = g_X[(b * 32 + c) * 256 + kl];
    }
    __syncthreads();
    int b = threadIdx.x >> 5, o = threadIdx.x & 31;
    float yr = 0.f, yi = 0.f;
    #pragma unroll
    for (int c0 = 0; c0 < 32; c0++) {
        float2 xv = Xs[b][c0];
        float2 wv = Ws[c0 * 32 + o];
        yr += xv.x * wv.x - xv.y * wv.y;
        yi += xv.x * wv.y + xv.y * wv.x;
    }
    g_Y[(b * 32 + o) * 256 + kl] = make_float2(yr, yi);
}

// K2c: H-axis inverse. B[b,o,h,l] = sum_k Y[k,l] e^{+2pi i k h/256}
__global__ void k2c() {
    __shared__ float2 Ys[256];
    int bo = blockIdx.x;                        // 128
    Ys[threadIdx.x] = g_Y[bo * 256 + threadIdx.x];
    __syncthreads();
    int h = threadIdx.x;
    float cstep = g_ct[h], sstep = g_st[h];     // e^{+2pi i h/256}
    float c = 1.f, s = 0.f;
    float br[16], bi[16];
    #pragma unroll
    for (int l = 0; l < 16; l++) { br[l] = 0.f; bi[l] = 0.f; }
    #pragma unroll
    for (int k = 0; k < 16; k++) {
        #pragma unroll
        for (int l = 0; l < 16; l++) {
            float2 y = Ys[k * 16 + l];
            br[l] += y.x * c - y.y * s;
            bi[l] += y.x * s + y.y * c;
        }
        float c2 = c * cstep - s * sstep;
        s = fmaf(c, sstep, s * cstep);
        c = c2;
    }
    float2* dst = g_Bf + ((long)bo * 256 + h) * 16;
    #pragma unroll
    for (int l = 0; l < 16; l++) dst[l] = make_float2(br[l], bi[l]);
}

// K3: W-axis inverse (irfft, DC imag dropped, x2 for l>=1, x 1/256) + bypass conv + GELU
__global__ void k3(const float* __restrict__ xin, float* __restrict__ xout,
                   const float* __restrict__ bw, const float* __restrict__ bb) {
    __shared__ float  xs[32 * 256];             // 32KB
    __shared__ float2 Bs[32 * 16];              // 4KB
    __shared__ float  bws[32 * 32];             // 4KB
    __shared__ float  bbs[32];
    int b = blockIdx.x >> 8, h = blockIdx.x & 255;
    for (int i = threadIdx.x; i < 8192; i += 256) {
        int c = i >> 8, w = i & 255;
        xs[i] = xin[(long)(b * 32 + c) * PIX + h * 256 + w];
    }
    for (int i = threadIdx.x; i < 512; i += 256)
        Bs[i] = g_Bf[((long)(b * 32 + (i >> 4)) * 256 + h) * 16 + (i & 15)];
    for (int i = threadIdx.x; i < 1024; i += 256) bws[i] = bw[i];
    if (threadIdx.x < 32) bbs[threadIdx.x] = bb[threadIdx.x];
    __syncthreads();
    int w = threadIdx.x;
    float cs = g_ct[w], ss = g_st[w];           // e^{+2pi i w/256}
    float cw[16], sw[16];
    cw[0] = 1.f; sw[0] = 0.f;
    #pragma unroll
    for (int l = 1; l < 16; l++) {
        cw[l] = cw[l - 1] * cs - sw[l - 1] * ss;
        sw[l] = fmaf(cw[l - 1], ss, sw[l - 1] * cs);
    }
    for (int o = 0; o < 32; o++) {
        const float2* Bo = Bs + o * 16;
        float spec = Bo[0].x;                   // DC: imaginary part dropped (C2R convention)
        #pragma unroll
        for (int l = 1; l < 16; l++)
            spec += 2.f * (Bo[l].x * cw[l] - Bo[l].y * sw[l]);
        spec *= (1.f / 256.f);
        float acc = bbs[o];
        #pragma unroll
        for (int i = 0; i < 32; i++)
            acc = fmaf(xs[i * 256 + w], bws[o * 32 + i], acc);
        float v = spec + acc;
        float g = 0.5f * v * (1.f + erff(v * 0.70710678118654752f));
        xout[(long)(b * 32 + o) * PIX + h * 256 + w] = g;
    }
}

// Projection: out[b,oh,h,w] = pb + sum_c xb[b,c,h,w] * pw[c]
__global__ void kproj(const float* __restrict__ xin, float* __restrict__ out,
                      const float* __restrict__ pw, const float* __restrict__ pb, int oh) {
    __shared__ float pws[32];
    int b = blockIdx.x >> 8, h = blockIdx.x & 255, w = threadIdx.x;
    if (threadIdx.x < 32) pws[threadIdx.x] = pw[threadIdx.x];
    __syncthreads();
    float acc = pb[0];
    #pragma unroll
    for (int c = 0; c < 32; c++)
        acc = fmaf(xin[(long)(b * 32 + c) * PIX + h * 256 + w], pws[c], acc);
    out[((long)(b * OC + oh) * 256 + h) * 256 + w] = acc;
}

extern "C" void kernel_launch(void* const* d_in, const int* in_sizes, int n_in,
                              void* d_out, int out_size) {
    const float* x      = (const float*)d_in[0];
    const float* lift_w = (const float*)d_in[1];
    const float* lift_b = (const float*)d_in[2];
    const float* wr     = (const float*)d_in[3];
    const float* wi     = (const float*)d_in[4];
    const float* byp_w  = (const float*)d_in[5];
    const float* byp_b  = (const float*)d_in[6];
    const float* proj_w = (const float*)d_in[7];
    const float* proj_b = (const float*)d_in[8];
    float* out = (float*)d_out;

    float *x0, *xa, *xb;
    float2* W;
    cudaGetSymbolAddress((void**)&x0, g_x0);
    cudaGetSymbolAddress((void**)&xa, g_xa);
    cudaGetSymbolAddress((void**)&xb, g_xb);
    cudaGetSymbolAddress((void**)&W,  g_W);

    init_tw<<<1, 256>>>();
    init_w<<<4096, 1024>>>(wr, wi);
    klift<<<(BB * CC * PIX) / 256, 256>>>(x, lift_w, lift_b);

    for (int oh = 0; oh < OC; oh++) {
        for (int n = 0; n < NB; n++) {
            const float* src = (n == 0) ? x0 : ((n & 1) ? xa : xb);
            float* dst = (n & 1) ? xb : xa;
            int ohn = oh * NB + n;
            k1 <<<2048, 256>>>(src);
            k2a<<<128, 256>>>();
            k2b<<<256, 128>>>(W + (long)ohn * MM * MM * CC * CC);
            k2c<<<128, 256>>>();
            k3 <<<1024, 256>>>(src, dst, byp_w + ohn * CC * CC, byp_b + ohn * CC);
        }
        kproj<<<1024, 256>>>(xb, out, proj_w, proj_b, oh);
    }
}

// round 2
// speedup vs baseline: 1.2949x; 1.2949x over previous
#include <cuda_runtime.h>
#include <cuda_bf16.h>
#include <math.h>

#define BB 4
#define CIN 3
#define CC 32
#define HH 256
#define WW 256
#define MM 16
#define NB 4
#define OC 4
#define PIX (HH*WW)

// Scratch (device globals: allocation-free)
__device__ float  g_x0[BB*CC*PIX];
__device__ float  g_xa[BB*CC*PIX];
__device__ float  g_xb[BB*CC*PIX];
__device__ float2 g_S [BB*HH*CC*MM];               // [b][h][c][m]
__device__ float2 g_X [BB*CC*MM*MM];               // [(b*32+c)][kl]
__device__ float2 g_X0[BB*CC*MM*MM];               // X of x0 (oh-invariant)
__device__ float2 g_Y [BB*CC*MM*MM];               // [(b*32+o)][kl]
__device__ float2 g_W [OC*NB*MM*MM*CC*CC];         // [ohn][kl][c][o]
__device__ float2 g_tw2[256];                      // (cos, sin)(2*pi*t/256)

__global__ void init_tw() {
    int t = threadIdx.x;
    double a = 6.283185307179586476925286766559 * (double)t / 256.0;
    g_tw2[t] = make_float2((float)cos(a), (float)sin(a));
}

// src [ohn][c][o][k][l] -> dst [ohn][k*16+l][c][o]
__global__ void init_w(const float* __restrict__ wr, const float* __restrict__ wi) {
    long d = (long)blockIdx.x * blockDim.x + threadIdx.x;   // 4194304
    int o   = (int)(d & 31);
    int c   = (int)((d >> 5) & 31);
    int kl  = (int)((d >> 10) & 255);
    int ohn = (int)(d >> 18);
    int k = kl >> 4, l = kl & 15;
    long s = ((((long)ohn * 32 + c) * 32 + o) * 16 + k) * 16 + l;
    g_W[d] = make_float2(wr[s], wi[s]);
}

__global__ void klift(const float* __restrict__ x, const float* __restrict__ lw,
                      const float* __restrict__ lb) {
    int idx = blockIdx.x * 256 + threadIdx.x;
    int pix = idx & (PIX - 1);
    int bc  = idx >> 16;
    int c = bc & 31, b = bc >> 5;
    float acc = lb[c];
    #pragma unroll
    for (int i = 0; i < CIN; i++)
        acc = fmaf(x[(b * CIN + i) * PIX + pix], lw[c * CIN + i], acc);
    g_x0[idx] = acc;
}

// K1: W-axis truncated DFT of x0 (runs once). S[b,h,c,m] = sum_w x * e^{-2pi i m w/256}
#define XSTR 261
__global__ void k1(const float* __restrict__ xin) {
    __shared__ float  xs[32 * XSTR];
    __shared__ float2 tws[256];
    int row0 = blockIdx.x * 32;   // row = (b*32+c)*256 + h
    for (int i = threadIdx.x; i < 8192; i += 256)
        xs[(i >> 8) * XSTR + (i & 255)] = xin[(long)row0 * 256 + i];
    if (threadIdx.x < 256) tws[threadIdx.x] = g_tw2[threadIdx.x];
    __syncthreads();
    int m = threadIdx.x >> 4;          // 0..15
    int rp = threadIdx.x & 15;         // rows rp, rp+16
    float ar0 = 0.f, ai0 = 0.f, ar1 = 0.f, ai1 = 0.f;
    const float* xp0 = xs + rp * XSTR;
    const float* xp1 = xs + (rp + 16) * XSTR;
    #pragma unroll 4
    for (int w = 0; w < 256; w++) {
        float2 tw = tws[(m * w) & 255];
        float v0 = xp0[w], v1 = xp1[w];
        ar0 = fmaf(v0, tw.x, ar0); ai0 = fmaf(v0, -tw.y, ai0);
        ar1 = fmaf(v1, tw.x, ar1); ai1 = fmaf(v1, -tw.y, ai1);
    }
    int ra = row0 + rp, rb = row0 + rp + 16;
    int ca = (ra >> 8) & 31, ba = ra >> 13, ha = ra & 255;
    int cb = (rb >> 8) & 31, bb_ = rb >> 13, hb = rb & 255;
    g_S[(((ba << 8) + ha) * 32 + ca) * 16 + m] = make_float2(ar0, ai0);
    g_S[(((bb_ << 8) + hb) * 32 + cb) * 16 + m] = make_float2(ar1, ai1);
}

// K2a: H-axis truncated DFT + ortho 1/256. X[bc][k*16+l] = (1/256) sum_h S[b,h,c,l] e^{-2pi i k h/256}
__global__ void k2a(float2* __restrict__ Xd) {
    __shared__ float2 Ss[256 * 16];
    __shared__ float2 tws[256];
    __shared__ float2 red[512];
    int bc = blockIdx.x, b = bc >> 5, c = bc & 31;
    for (int i = threadIdx.x; i < 4096; i += 512) {
        int h = i >> 4, m = i & 15;
        Ss[i] = g_S[(((b << 8) + h) * 32 + c) * 16 + m];
    }
    if (threadIdx.x < 256) tws[threadIdx.x] = g_tw2[threadIdx.x];
    __syncthreads();
    int kl = threadIdx.x & 255, half = threadIdx.x >> 8;
    int k = kl >> 4, l = kl & 15;
    float ar = 0.f, ai = 0.f;
    int h0 = half * 128;
    #pragma unroll 4
    for (int h = h0; h < h0 + 128; h++) {
        float2 tw = tws[(k * h) & 255];
        float2 v = Ss[h * 16 + l];
        ar += v.x * tw.x + v.y * tw.y;
        ai += v.y * tw.x - v.x * tw.y;
    }
    red[threadIdx.x] = make_float2(ar, ai);
    __syncthreads();
    if (threadIdx.x < 256) {
        float2 a = red[threadIdx.x], d = red[threadIdx.x + 256];
        Xd[bc * 256 + threadIdx.x] =
            make_float2((a.x + d.x) * (1.f / 256.f), (a.y + d.y) * (1.f / 256.f));
    }
}

// K2b: channel mix per kl
__global__ void k2b(const float2* __restrict__ Wt, const float2* __restrict__ Xs_g) {
    __shared__ float2 Ws[32 * 32];
    __shared__ float2 Xs[4][32];
    int kl = blockIdx.x;
    for (int i = threadIdx.x; i < 1024; i += 128) Ws[i] = Wt[(long)kl * 1024 + i];
    {
        int b = threadIdx.x >> 5, c = threadIdx.x & 31;
        Xs[b][c] = Xs_g[(b * 32 + c) * 256 + kl];
    }
    __syncthreads();
    int b = threadIdx.x >> 5, o = threadIdx.x & 31;
    float yr = 0.f, yi = 0.f;
    #pragma unroll
    for (int c0 = 0; c0 < 32; c0++) {
        float2 xv = Xs[b][c0];
        float2 wv = Ws[c0 * 32 + o];
        yr += xv.x * wv.x - xv.y * wv.y;
        yi += xv.x * wv.y + xv.y * wv.x;
    }
    g_Y[(b * 32 + o) * 256 + kl] = make_float2(yr, yi);
}

// K3s: per (b,h): H-inverse (folded k2c) + W-inverse + bypass + GELU + next-iter W-DFT (folded k1)
__global__ void __launch_bounds__(256) k3s(
    const float* __restrict__ xin, float* __restrict__ xout,
    const float* __restrict__ bw, const float* __restrict__ bb) {
    __shared__ float  gs[32 * XSTR];   // 33.4KB
    __shared__ float2 Bs[32 * 16];
    __shared__ float4 bws4[256];
    __shared__ float2 tws[256];
    __shared__ float  bbs[32];
    int h = blockIdx.x, b = blockIdx.y;
    int t = threadIdx.x;               // = w
    if (t < 256) { tws[t] = g_tw2[t]; bws4[t] = ((const float4*)bw)[t]; }
    if (t < 32) bbs[t] = bb[t];

    // bypass source column -> registers (coalesced)
    float xr[32];
    #pragma unroll
    for (int i = 0; i < 32; i++)
        xr[i] = xin[((long)(b * 32 + i) << 16) + (h << 8) + t];
    __syncthreads();

    // Phase B: Bs[o][l] = sum_k Y[b,o,k,l] e^{+2pi i k h/256}
    const float2* Yb = g_Y + (long)b * 32 * 256;
    #pragma unroll
    for (int rep = 0; rep < 2; rep++) {
        int idx = t + rep * 256;
        int o = idx >> 4, l = idx & 15;
        float br = 0.f, bi = 0.f;
        #pragma unroll
        for (int k = 0; k < 16; k++) {
            float2 y = Yb[o * 256 + k * 16 + l];
            float2 tw = tws[(k * h) & 255];
            br += y.x * tw.x - y.y * tw.y;
            bi += y.x * tw.y + y.y * tw.x;
        }
        Bs[idx] = make_float2(br, bi);
    }
    __syncthreads();

    // Phase C: spatial + bypass + GELU
    float cw[16], sw[16];
    cw[0] = 1.f; sw[0] = 0.f;
    #pragma unroll
    for (int l = 1; l < 16; l++) {
        float2 tw = tws[(l * t) & 255];
        cw[l] = tw.x; sw[l] = tw.y;
    }
    for (int o = 0; o < 32; o++) {
        const float2* Bo = Bs + o * 16;
        float spec = Bo[0].x;                  // DC imag dropped (C2R)
        #pragma unroll
        for (int l = 1; l < 16; l++)
            spec = fmaf(2.f, Bo[l].x * cw[l] - Bo[l].y * sw[l], spec);
        float acc = bbs[o];
        const float4* bwo = bws4 + o * 8;
        #pragma unroll
        for (int i = 0; i < 8; i++) {
            float4 w4 = bwo[i];
            acc = fmaf(xr[4 * i + 0], w4.x, acc);
            acc = fmaf(xr[4 * i + 1], w4.y, acc);
            acc = fmaf(xr[4 * i + 2], w4.z, acc);
            acc = fmaf(xr[4 * i + 3], w4.w, acc);
        }
        float v = fmaf(spec, 1.f / 256.f, acc);
        float g = 0.5f * v * (1.f + erff(v * 0.70710678118654752f));
        xout[((long)(b * 32 + o) << 16) + (h << 8) + t] = g;
        gs[o * XSTR + t] = g;
    }
    __syncthreads();

    // Phase D: next-iter W-DFT from smem g values
    {
        int o = t & 31, m = t >> 5, m1 = m + 8;
        float ar0 = 0.f, ai0 = 0.f, ar1 = 0.f, ai1 = 0.f;
        const float* go = gs + o * XSTR;
        #pragma unroll 4
        for (int w = 0; w < 256; w++) {
            float v = go[w];
            float2 t0 = tws[(m * w) & 255];
            float2 t1 = tws[(m1 * w) & 255];
            ar0 = fmaf(v, t0.x, ar0); ai0 = fmaf(v, -t0.y, ai0);
            ar1 = fmaf(v, t1.x, ar1); ai1 = fmaf(v, -t1.y, ai1);
        }
        Bs[o * 16 + m]  = make_float2(ar0, ai0);
        Bs[o * 16 + m1] = make_float2(ar1, ai1);
    }
    __syncthreads();
    float2* Sd = g_S + ((long)(b * 256 + h) * 32) * 16;
    for (int i = t; i < 512; i += 256) Sd[i] = Bs[i];
}

// K3p: last block of chain — spatial + bypass + GELU + projection (no dst, no S)
__global__ void __launch_bounds__(256) k3p(
    const float* __restrict__ xin, float* __restrict__ out,
    const float* __restrict__ bw, const float* __restrict__ bb,
    const float* __restrict__ pw, const float* __restrict__ pb, int oh) {
    __shared__ float2 Bs[32 * 16];
    __shared__ float4 bws4[256];
    __shared__ float2 tws[256];
    __shared__ float  bbs[32];
    __shared__ float  pws[32];
    int h = blockIdx.x, b = blockIdx.y;
    int t = threadIdx.x;
    if (t < 256) { tws[t] = g_tw2[t]; bws4[t] = ((const float4*)bw)[t]; }
    if (t < 32) { bbs[t] = bb[t]; pws[t] = pw[t]; }

    float xr[32];
    #pragma unroll
    for (int i = 0; i < 32; i++)
        xr[i] = xin[((long)(b * 32 + i) << 16) + (h << 8) + t];
    __syncthreads();

    const float2* Yb = g_Y + (long)b * 32 * 256;
    #pragma unroll
    for (int rep = 0; rep < 2; rep++) {
        int idx = t + rep * 256;
        int o = idx >> 4, l = idx & 15;
        float br = 0.f, bi = 0.f;
        #pragma unroll
        for (int k = 0; k < 16; k++) {
            float2 y = Yb[o * 256 + k * 16 + l];
            float2 tw = tws[(k * h) & 255];
            br += y.x * tw.x - y.y * tw.y;
            bi += y.x * tw.y + y.y * tw.x;
        }
        Bs[idx] = make_float2(br, bi);
    }
    __syncthreads();

    float cw[16], sw[16];
    cw[0] = 1.f; sw[0] = 0.f;
    #pragma unroll
    for (int l = 1; l < 16; l++) {
        float2 tw = tws[(l * t) & 255];
        cw[l] = tw.x; sw[l] = tw.y;
    }
    float pacc = 0.f;
    for (int o = 0; o < 32; o++) {
        const float2* Bo = Bs + o * 16;
        float spec = Bo[0].x;
        #pragma unroll
        for (int l = 1; l < 16; l++)
            spec = fmaf(2.f, Bo[l].x * cw[l] - Bo[l].y * sw[l], spec);
        float acc = bbs[o];
        const float4* bwo = bws4 + o * 8;
        #pragma unroll
        for (int i = 0; i < 8; i++) {
            float4 w4 = bwo[i];
            acc = fmaf(xr[4 * i + 0], w4.x, acc);
            acc = fmaf(xr[4 * i + 1], w4.y, acc);
            acc = fmaf(xr[4 * i + 2], w4.z, acc);
            acc = fmaf(xr[4 * i + 3], w4.w, acc);
        }
        float v = fmaf(spec, 1.f / 256.f, acc);
        float g = 0.5f * v * (1.f + erff(v * 0.70710678118654752f));
        pacc = fmaf(g, pws[o], pacc);
    }
    out[((long)(b * OC + oh) * 256 + h) * 256 + t] = pacc + pb[0];
}

extern "C" void kernel_launch(void* const* d_in, const int* in_sizes, int n_in,
                              void* d_out, int out_size) {
    const float* x      = (const float*)d_in[0];
    const float* lift_w = (const float*)d_in[1];
    const float* lift_b = (const float*)d_in[2];
    const float* wr     = (const float*)d_in[3];
    const float* wi     = (const float*)d_in[4];
    const float* byp_w  = (const float*)d_in[5];
    const float* byp_b  = (const float*)d_in[6];
    const float* proj_w = (const float*)d_in[7];
    const float* proj_b = (const float*)d_in[8];
    float* out = (float*)d_out;

    float *x0, *xa, *xb;
    float2 *W, *X, *X0;
    cudaGetSymbolAddress((void**)&x0, g_x0);
    cudaGetSymbolAddress((void**)&xa, g_xa);
    cudaGetSymbolAddress((void**)&xb, g_xb);
    cudaGetSymbolAddress((void**)&W,  g_W);
    cudaGetSymbolAddress((void**)&X,  g_X);
    cudaGetSymbolAddress((void**)&X0, g_X0);

    init_tw<<<1, 256>>>();
    init_w<<<4096, 1024>>>(wr, wi);
    klift<<<(BB * CC * PIX) / 256, 256>>>(x, lift_w, lift_b);
    k1<<<1024, 256>>>(x0);          // S(x0) — shared across oh
    k2a<<<128, 512>>>(X0);          // X(x0) — shared across oh

    dim3 g3(256, 4);
    for (int oh = 0; oh < OC; oh++) {
        // n = 0
        int ohn = oh * NB;
        k2b<<<256, 128>>>(W + (long)ohn * 256 * 1024, X0);
        k3s<<<g3, 256>>>(x0, xa, byp_w + ohn * CC * CC, byp_b + ohn * CC);
        // n = 1
        ohn++;
        k2a<<<128, 512>>>(X);
        k2b<<<256, 128>>>(W + (long)ohn * 256 * 1024, X);
        k3s<<<g3, 256>>>(xa, xb, byp_w + ohn * CC * CC, byp_b + ohn * CC);
        // n = 2
        ohn++;
        k2a<<<128, 512>>>(X);
        k2b<<<256, 128>>>(W + (long)ohn * 256 * 1024, X);
        k3s<<<g3, 256>>>(xb, xa, byp_w + ohn * CC * CC, byp_b + ohn * CC);
        // n = 3 (fused projection)
        ohn++;
        k2a<<<128, 512>>>(X);
        k2b<<<256, 128>>>(W + (long)ohn * 256 * 1024, X);
        k3p<<<g3, 256>>>(xa, out, byp_w + ohn * CC * CC, byp_b + ohn * CC,
                         proj_w, proj_b, oh);
    }
}

// round 3
// speedup vs baseline: 1.7282x; 1.3346x over previous
#include <cuda_runtime.h>
#include <cuda_bf16.h>
#include <math.h>

#define BB 4
#define CIN 3
#define CC 32
#define HH 256
#define WW 256
#define MM 16
#define NB 4
#define OC 4
#define PIX (HH*WW)
#define XSTR 261

// Scratch (device globals: allocation-free)
__device__ float  g_x0[BB*CC*PIX];                 // 32MB
__device__ float  g_xa[OC*BB*CC*PIX];              // 128MB  [boh][c][pix]
__device__ float  g_xb[OC*BB*CC*PIX];              // 128MB
__device__ float2 g_S [OC*BB*MM*HH*CC];            // [boh][m][h][c] (slots 0..3 reused for S(x0) by b)
__device__ float2 g_X [OC*BB*CC*MM*MM];            // [boh*32+c][kl]
__device__ float2 g_X0[BB*CC*MM*MM];               // [b*32+c][kl]
__device__ float2 g_Y [OC*BB*CC*MM*MM];            // [boh*32+o][kl]
__device__ float2 g_W [OC*NB*MM*MM*CC*CC];         // [ohn][kl][c][o]
__device__ float2 g_tw2[256];                      // (cos,sin)(2*pi*t/256)

__global__ void init_tw() {
    int t = threadIdx.x;
    double a = 6.283185307179586476925286766559 * (double)t / 256.0;
    g_tw2[t] = make_float2((float)cos(a), (float)sin(a));
}

// src [ohn][c][o][k][l] -> dst [ohn][k*16+l][c][o]
__global__ void init_w(const float* __restrict__ wr, const float* __restrict__ wi) {
    long d = (long)blockIdx.x * blockDim.x + threadIdx.x;   // 4194304
    int o   = (int)(d & 31);
    int c   = (int)((d >> 5) & 31);
    int kl  = (int)((d >> 10) & 255);
    int ohn = (int)(d >> 18);
    int k = kl >> 4, l = kl & 15;
    long s = ((((long)ohn * 32 + c) * 32 + o) * 16 + k) * 16 + l;
    g_W[d] = make_float2(wr[s], wi[s]);
}

__global__ void klift(const float* __restrict__ x, const float* __restrict__ lw,
                      const float* __restrict__ lb) {
    int idx = blockIdx.x * 256 + threadIdx.x;
    int pix = idx & (PIX - 1);
    int bc  = idx >> 16;
    int c = bc & 31, b = bc >> 5;
    float acc = lb[c];
    #pragma unroll
    for (int i = 0; i < CIN; i++)
        acc = fmaf(x[(b * CIN + i) * PIX + pix], lw[c * CIN + i], acc);
    g_x0[idx] = acc;
}

// K1 (once): W-axis truncated DFT of x0 -> S[b][m][h][c]
__global__ void k1(const float* __restrict__ xin) {
    __shared__ float  xs[32 * XSTR];
    __shared__ float2 tws[256];
    int row0 = blockIdx.x * 32;                 // row = (b*32+c)*256 + h
    for (int i = threadIdx.x; i < 8192; i += 256)
        xs[(i >> 8) * XSTR + (i & 255)] = xin[(long)row0 * 256 + i];
    tws[threadIdx.x] = g_tw2[threadIdx.x];
    __syncthreads();
    int b = row0 >> 13, c = (row0 >> 8) & 31, h0 = row0 & 255;
    int m = threadIdx.x >> 4, jp = threadIdx.x & 15;
    float sgn = (m & 1) ? -1.f : 1.f;
    float ar0 = 0.f, ai0 = 0.f, ar1 = 0.f, ai1 = 0.f;
    const float* xp0 = xs + jp * XSTR;
    const float* xp1 = xs + (jp + 16) * XSTR;
    #pragma unroll 4
    for (int w = 0; w < 128; w++) {
        float2 tw = tws[(m * w) & 255];
        float u0 = fmaf(sgn, xp0[w + 128], xp0[w]);
        float u1 = fmaf(sgn, xp1[w + 128], xp1[w]);
        ar0 = fmaf(u0, tw.x, ar0); ai0 = fmaf(u0, -tw.y, ai0);
        ar1 = fmaf(u1, tw.x, ar1); ai1 = fmaf(u1, -tw.y, ai1);
    }
    g_S[(((b * 16 + m) * 256) + h0 + jp)      * 32 + c] = make_float2(ar0, ai0);
    g_S[(((b * 16 + m) * 256) + h0 + jp + 16) * 32 + c] = make_float2(ar1, ai1);
}

// K2a: H-axis truncated DFT (+1/256). grid(16 l, nb, 2 chalf), 256 thr.
// X[(g*32+c)*256 + k*16 + l] = (1/256) sum_h S[g][l][h][c] e^{-2pi i k h/256}
__global__ void k2a(const float2* __restrict__ S, float2* __restrict__ X) {
    __shared__ float2 Ss[256 * 16];             // 32KB [h][c16]
    __shared__ float2 tws[256];
    int l = blockIdx.x, g = blockIdx.y, chalf = blockIdx.z;
    const float2* Sp = S + ((long)(g * 16 + l) * 256) * 32 + chalf * 16;
    for (int i = threadIdx.x; i < 4096; i += 256)
        Ss[i] = Sp[(i >> 4) * 32 + (i & 15)];
    tws[threadIdx.x] = g_tw2[threadIdx.x];
    __syncthreads();
    int c16 = threadIdx.x & 15, k = threadIdx.x >> 4;
    float sgn = (k & 1) ? -1.f : 1.f;
    float ar = 0.f, ai = 0.f;
    #pragma unroll 4
    for (int h = 0; h < 128; h++) {
        float2 v0 = Ss[h * 16 + c16];
        float2 v1 = Ss[(h + 128) * 16 + c16];
        float ux = fmaf(sgn, v1.x, v0.x);
        float uy = fmaf(sgn, v1.y, v0.y);
        float2 tw = tws[(k * h) & 255];
        ar += ux * tw.x + uy * tw.y;
        ai += uy * tw.x - ux * tw.y;
    }
    int c = chalf * 16 + c16;
    X[((long)(g * 32 + c)) * 256 + k * 16 + l] =
        make_float2(ar * (1.f / 256.f), ai * (1.f / 256.f));
}

// K2b: channel mix. grid(256 kl, OC oh), 128 thr.
__global__ void k2b(const float2* __restrict__ X, int x_oh_mult, int n) {
    __shared__ float2 Ws[32 * 32];
    __shared__ float2 Xs[4][32];
    int kl = blockIdx.x, oh = blockIdx.y;
    const float2* Wt = g_W + ((long)(oh * NB + n) * 256 + kl) * 1024;
    for (int i = threadIdx.x; i < 1024; i += 128) Ws[i] = Wt[i];
    {
        int b = threadIdx.x >> 5, c = threadIdx.x & 31;
        Xs[b][c] = X[((long)((oh * x_oh_mult + b) * 32 + c)) * 256 + kl];
    }
    __syncthreads();
    int b = threadIdx.x >> 5, o = threadIdx.x & 31;
    float yr = 0.f, yi = 0.f;
    #pragma unroll
    for (int c0 = 0; c0 < 32; c0++) {
        float2 xv = Xs[b][c0];
        float2 wv = Ws[c0 * 32 + o];
        yr += xv.x * wv.x - xv.y * wv.y;
        yi += xv.x * wv.y + xv.y * wv.x;
    }
    g_Y[((long)((oh * 4 + b) * 32 + o)) * 256 + kl] = make_float2(yr, yi);
}

// K3s: per (h, boh): H-inverse + W-inverse + bypass + GELU + next W-DFT
__global__ void __launch_bounds__(256) k3s(
    const float* __restrict__ xin, int in_nb, float* __restrict__ xout,
    const float* __restrict__ byp_w, const float* __restrict__ byp_b, int n) {
    __shared__ float  gs[32 * XSTR];
    __shared__ float2 Bs[32 * 16];
    __shared__ float4 bws4[256];
    __shared__ float2 tws[256];
    __shared__ float  bbs[32];
    int h = blockIdx.x, boh = blockIdx.y;
    int b = boh & 3, oh = boh >> 2;
    int ohn = oh * NB + n;
    int t = threadIdx.x;
    tws[t] = g_tw2[t];
    bws4[t] = ((const float4*)(byp_w + ohn * 1024))[t];
    if (t < 32) bbs[t] = byp_b[ohn * 32 + t];

    int inb = (in_nb == 4) ? b : boh;
    float xr[32];
    #pragma unroll
    for (int i = 0; i < 32; i++)
        xr[i] = xin[((long)(inb * 32 + i) << 16) + (h << 8) + t];
    __syncthreads();

    // Phase B: Bs[o][l] = sum_k Y[boh,o,k,l] e^{+2pi i k h/256}
    const float2* Yb = g_Y + (long)boh * 8192;
    #pragma unroll
    for (int rep = 0; rep < 2; rep++) {
        int idx = t + rep * 256;
        int o = idx >> 4, l = idx & 15;
        float br = 0.f, bi = 0.f;
        #pragma unroll
        for (int k = 0; k < 16; k++) {
            float2 y = Yb[o * 256 + k * 16 + l];
            float2 tw = tws[(k * h) & 255];
            br += y.x * tw.x - y.y * tw.y;
            bi += y.x * tw.y + y.y * tw.x;
        }
        Bs[idx] = make_float2(br, bi);
    }
    __syncthreads();

    // Phase C: spatial inverse + bypass + GELU
    float cw[16], sw[16];
    cw[0] = 1.f; sw[0] = 0.f;
    #pragma unroll
    for (int l = 1; l < 16; l++) {
        float2 tw = tws[(l * t) & 255];
        cw[l] = tw.x; sw[l] = tw.y;
    }
    for (int o = 0; o < 32; o++) {
        const float2* Bo = Bs + o * 16;
        float spec = Bo[0].x;                   // DC imag dropped (C2R)
        #pragma unroll
        for (int l = 1; l < 16; l++)
            spec = fmaf(2.f, Bo[l].x * cw[l] - Bo[l].y * sw[l], spec);
        float acc = bbs[o];
        const float4* bwo = bws4 + o * 8;
        #pragma unroll
        for (int i = 0; i < 8; i++) {
            float4 w4 = bwo[i];
            acc = fmaf(xr[4 * i + 0], w4.x, acc);
            acc = fmaf(xr[4 * i + 1], w4.y, acc);
            acc = fmaf(xr[4 * i + 2], w4.z, acc);
            acc = fmaf(xr[4 * i + 3], w4.w, acc);
        }
        float v = fmaf(spec, 1.f / 256.f, acc);
        float g = 0.5f * v * (1.f + erff(v * 0.70710678118654752f));
        xout[((long)(boh * 32 + o) << 16) + (h << 8) + t] = g;
        gs[o * XSTR + t] = g;
    }
    __syncthreads();

    // Phase D: next-iteration W-DFT -> S[boh][m][h][c=o]
    {
        int o = t & 31, m = t >> 5, m1 = m + 8;
        float sgn = (m & 1) ? -1.f : 1.f;       // m and m+8 share parity
        float ar0 = 0.f, ai0 = 0.f, ar1 = 0.f, ai1 = 0.f;
        const float* go = gs + o * XSTR;
        #pragma unroll 4
        for (int w = 0; w < 128; w++) {
            float u = fmaf(sgn, go[w + 128], go[w]);
            float2 t0 = tws[(m * w) & 255];
            float2 t1 = tws[(m1 * w) & 255];
            ar0 = fmaf(u, t0.x, ar0); ai0 = fmaf(u, -t0.y, ai0);
            ar1 = fmaf(u, t1.x, ar1); ai1 = fmaf(u, -t1.y, ai1);
        }
        g_S[(((long)(boh * 16 + m ) * 256) + h) * 32 + o] = make_float2(ar0, ai0);
        g_S[(((long)(boh * 16 + m1) * 256) + h) * 32 + o] = make_float2(ar1, ai1);
    }
}

// K3p: last block in chain — fused projection, no S/xout stores
__global__ void __launch_bounds__(256) k3p(
    const float* __restrict__ xin, float* __restrict__ out,
    const float* __restrict__ byp_w, const float* __restrict__ byp_b,
    const float* __restrict__ pw, const float* __restrict__ pb, int n) {
    __shared__ float2 Bs[32 * 16];
    __shared__ float4 bws4[256];
    __shared__ float2 tws[256];
    __shared__ float  bbs[32];
    __shared__ float  pws[32];
    int h = blockIdx.x, boh = blockIdx.y;
    int b = boh & 3, oh = boh >> 2;
    int ohn = oh * NB + n;
    int t = threadIdx.x;
    tws[t] = g_tw2[t];
    bws4[t] = ((const float4*)(byp_w + ohn * 1024))[t];
    if (t < 32) { bbs[t] = byp_b[ohn * 32 + t]; pws[t] = pw[t]; }

    float xr[32];
    #pragma unroll
    for (int i = 0; i < 32; i++)
        xr[i] = xin[((long)(boh * 32 + i) << 16) + (h << 8) + t];
    __syncthreads();

    const float2* Yb = g_Y + (long)boh * 8192;
    #pragma unroll
    for (int rep = 0; rep < 2; rep++) {
        int idx = t + rep * 256;
        int o = idx >> 4, l = idx & 15;
        float br = 0.f, bi = 0.f;
        #pragma unroll
        for (int k = 0; k < 16; k++) {
            float2 y = Yb[o * 256 + k * 16 + l];
            float2 tw = tws[(k * h) & 255];
            br += y.x * tw.x - y.y * tw.y;
            bi += y.x * tw.y + y.y * tw.x;
        }
        Bs[idx] = make_float2(br, bi);
    }
    __syncthreads();

    float cw[16], sw[16];
    cw[0] = 1.f; sw[0] = 0.f;
    #pragma unroll
    for (int l = 1; l < 16; l++) {
        float2 tw = tws[(l * t) & 255];
        cw[l] = tw.x; sw[l] = tw.y;
    }
    float pacc = 0.f;
    for (int o = 0; o < 32; o++) {
        const float2* Bo = Bs + o * 16;
        float spec = Bo[0].x;
        #pragma unroll
        for (int l = 1; l < 16; l++)
            spec = fmaf(2.f, Bo[l].x * cw[l] - Bo[l].y * sw[l], spec);
        float acc = bbs[o];
        const float4* bwo = bws4 + o * 8;
        #pragma unroll
        for (int i = 0; i < 8; i++) {
            float4 w4 = bwo[i];
            acc = fmaf(xr[4 * i + 0], w4.x, acc);
            acc = fmaf(xr[4 * i + 1], w4.y, acc);
            acc = fmaf(xr[4 * i + 2], w4.z, acc);
            acc = fmaf(xr[4 * i + 3], w4.w, acc);
        }
        float v = fmaf(spec, 1.f / 256.f, acc);
        float g = 0.5f * v * (1.f + erff(v * 0.70710678118654752f));
        pacc = fmaf(g, pws[o], pacc);
    }
    out[((long)(b * OC + oh) * 256 + h) * 256 + t] = pacc + pb[0];
}

extern "C" void kernel_launch(void* const* d_in, const int* in_sizes, int n_in,
                              void* d_out, int out_size) {
    const float* x      = (const float*)d_in[0];
    const float* lift_w = (const float*)d_in[1];
    const float* lift_b = (const float*)d_in[2];
    const float* wr     = (const float*)d_in[3];
    const float* wi     = (const float*)d_in[4];
    const float* byp_w  = (const float*)d_in[5];
    const float* byp_b  = (const float*)d_in[6];
    const float* proj_w = (const float*)d_in[7];
    const float* proj_b = (const float*)d_in[8];
    float* out = (float*)d_out;

    float *x0, *xa, *xb;
    float2 *S, *X, *X0;
    cudaGetSymbolAddress((void**)&x0, g_x0);
    cudaGetSymbolAddress((void**)&xa, g_xa);
    cudaGetSymbolAddress((void**)&xb, g_xb);
    cudaGetSymbolAddress((void**)&S,  g_S);
    cudaGetSymbolAddress((void**)&X,  g_X);
    cudaGetSymbolAddress((void**)&X0, g_X0);

    init_tw<<<1, 256>>>();
    init_w<<<4096, 1024>>>(wr, wi);
    klift<<<(BB * CC * PIX) / 256, 256>>>(x, lift_w, lift_b);
    k1<<<1024, 256>>>(x0);                          // S(x0) into slots [b]
    k2a<<<dim3(16, 4, 2), 256>>>(S, X0);            // X(x0), shared across oh

    dim3 g3(256, 16);
    // n = 0 (all oh concurrent)
    k2b<<<dim3(256, OC), 128>>>(X0, 0, 0);
    k3s<<<g3, 256>>>(x0, 4, xa, byp_w, byp_b, 0);
    // n = 1
    k2a<<<dim3(16, 16, 2), 256>>>(S, X);
    k2b<<<dim3(256, OC), 128>>>(X, 4, 1);
    k3s<<<g3, 256>>>(xa, 16, xb, byp_w, byp_b, 1);
    // n = 2
    k2a<<<dim3(16, 16, 2), 256>>>(S, X);
    k2b<<<dim3(256, OC), 128>>>(X, 4, 2);
    k3s<<<g3, 256>>>(xb, 16, xa, byp_w, byp_b, 2);
    // n = 3 (fused projection)
    k2a<<<dim3(16, 16, 2), 256>>>(S, X);
    k2b<<<dim3(256, OC), 128>>>(X, 4, 3);
    k3p<<<g3, 256>>>(xa, out, byp_w, byp_b, proj_w, proj_b, 3);
}